// round 11
// baseline (speedup 1.0000x reference)
#include <cuda_runtime.h>
#include <math.h>
#include <stdint.h>

// LatentOddityQuantizer round 11: int8 IMMA in the 2-CTA/SM shape.
// BM=128, BN=64, 4 warps (warp tile 32x64: 16 MMA / 6 ldsm per k-step preserved),
// single barrier per chunk, 3-stage cp.async, register double-buffered k-steps.
// dist = [triW(G)|Gz]·[tri(e x e)|-2e] / 96 + zGz(fp32); exact s32 accumulation.

typedef unsigned int u32;

#define GAMMA_F 10.0f

constexpr int D     = 64;
constexpr int NPOS  = 2048;
constexpr int KCW   = 1024;
constexpr int TRI   = 2080;           // 64*65/2
constexpr int KDIM  = 2176;           // 2080 tri + 64 linear + 32 pad = 17*128
constexpr int BK    = 128;            // int8 elems per chunk (128 B rows)
constexpr int NCHUNK = KDIM / BK;     // 17
constexpr int BM    = 128;
constexpr int BN    = 64;
constexpr int NTILES = KCW / BN;      // 16
constexpr int NSTAGE = 3;
constexpr int TPB   = 128;            // 4 warps, warp tile 32x64
constexpr int TILE_A = BM * BK;                   // 16 KB
constexpr int TILE_B = BN * BK;                   // 8 KB
constexpr int STAGE_BYTES = TILE_A + TILE_B;      // 24 KB
constexpr int PART_BYTES  = 128 * 8;
constexpr int SMEM_TOTAL  = NSTAGE * STAGE_BYTES + PART_BYTES;  // ~74.8 KB -> 2 CTAs/SM

constexpr float SCALE_A   = 16.f;
constexpr float SCALE_B   = 6.f;
constexpr float INV_SCALE = 1.f / (16.f * 6.f);

// ---------------- device scratch ----------------
__device__ __align__(16) signed char gA[(size_t)NPOS * KDIM];
__device__ __align__(16) signed char gB[(size_t)KCW * KDIM];
__device__ float  gQ[NPOS];
__device__ float2 g_part[(size_t)NPOS * NTILES];
__device__ int    g_cnt[16];
__device__ float  g_sim_scratch[(size_t)NPOS * KCW];

static __device__ __forceinline__ u32 smem_u32(const void* p) {
    u32 a;
    asm("{ .reg .u64 t; cvta.to.shared.u64 t, %1; cvt.u32.u64 %0, t; }" : "=r"(a) : "l"(p));
    return a;
}
static __device__ __forceinline__ u32 swz(u32 b) { return b ^ ((b >> 3) & 0x70); }
static __device__ __forceinline__ void cp_async16(u32 dst, const void* src) {
    asm volatile("cp.async.cg.shared.global [%0], [%1], 16;" :: "r"(dst), "l"(src));
}
static __device__ __forceinline__ void ldsm4(u32* r, u32 addr) {
    asm volatile("ldmatrix.sync.aligned.m8n8.x4.shared.b16 {%0,%1,%2,%3}, [%4];"
                 : "=r"(r[0]), "=r"(r[1]), "=r"(r[2]), "=r"(r[3]) : "r"(addr));
}
static __device__ __forceinline__ void mma_s8(int* c, const u32* a, const u32* b) {
    asm volatile(
        "mma.sync.aligned.m16n8k32.row.col.s32.s8.s8.s32 "
        "{%0,%1,%2,%3}, {%4,%5,%6,%7}, {%8,%9}, {%0,%1,%2,%3};"
        : "+r"(c[0]), "+r"(c[1]), "+r"(c[2]), "+r"(c[3])
        : "r"(a[0]), "r"(a[1]), "r"(a[2]), "r"(a[3]), "r"(b[0]), "r"(b[1]));
}
static __device__ __forceinline__ signed char quant(float v, float mult) {
    int x = __float2int_rn(v * mult);
    x = max(-127, min(127, x));
    return (signed char)x;
}

// triangle bookkeeping: base(r) = r*(129-r)/2
static __device__ __forceinline__ int tri_base(int r) { return (r * (129 - r)) >> 1; }
static __device__ __forceinline__ int tri_row(int f) {
    float s = sqrtf((float)(16641 - 8 * f));
    int r = (int)((129.f - s) * 0.5f);
    if (tri_base(r + 1) <= f) ++r;
    if (tri_base(r) > f) --r;
    return r;
}

// ---------------- merged build: [0,NPOS) -> A rows (+gQ), [NPOS,..) -> B rows ----
__global__ __launch_bounds__(128)
void build_kernel(const float* __restrict__ z, const float* __restrict__ G,
                  const float* __restrict__ E) {
    __shared__ float zs[D], vs[D], qp[2];
    __shared__ __align__(16) signed char stage[KDIM];
    const int b = blockIdx.x, t = threadIdx.x;

    if (b < NPOS) {
        const int n = b;
        const float* Gn = G + (size_t)n * D * D;
        if (t < D) zs[t] = z[n * D + t];
        __syncthreads();
        if (t < D) {
            float acc = 0.f;
            #pragma unroll 8
            for (int i = 0; i < D; ++i) acc = fmaf(Gn[i * D + t], zs[i], acc);
            vs[t] = acc;
            float p = zs[t] * acc;
            #pragma unroll
            for (int o = 16; o; o >>= 1) p += __shfl_down_sync(0xffffffffu, p, o);
            if ((t & 31) == 0) qp[t >> 5] = p;
        }
        __syncthreads();
        if (t == 0) gQ[n] = qp[0] + qp[1];
        #pragma unroll
        for (int i = 0; i < 17; ++i) {
            int f = t + i * 128;
            if (f < TRI) {
                int r = tri_row(f);
                int c = r + (f - tri_base(r));
                float g = Gn[r * D + c];
                stage[f] = quant(r == c ? g : 2.f * g, SCALE_A);
            }
        }
        if (t < D) stage[TRI + t] = quant(vs[t], SCALE_A);
        for (int f = TRI + D + t; f < KDIM; f += 128) stage[f] = 0;
        __syncthreads();
        uint4* dst = reinterpret_cast<uint4*>(gA + (size_t)n * KDIM);
        const uint4* src = reinterpret_cast<const uint4*>(stage);
        #pragma unroll
        for (int i = 0; i < 2; ++i) {
            int idx = t + i * 128;
            if (idx < KDIM / 16) dst[idx] = src[idx];
        }
    } else {
        const int k = b - NPOS;
        if (t < D) zs[t] = E[(size_t)k * D + t];
        __syncthreads();
        #pragma unroll
        for (int i = 0; i < 17; ++i) {
            int f = t + i * 128;
            if (f < TRI) {
                int r = tri_row(f);
                int c = r + (f - tri_base(r));
                stage[f] = quant(zs[r] * zs[c], SCALE_B);
            }
        }
        if (t < D) stage[TRI + t] = quant(-2.f * zs[t], SCALE_B);
        for (int f = TRI + D + t; f < KDIM; f += 128) stage[f] = 0;
        __syncthreads();
        uint4* dst = reinterpret_cast<uint4*>(gB + (size_t)k * KDIM);
        const uint4* src = reinterpret_cast<const uint4*>(stage);
        #pragma unroll
        for (int i = 0; i < 2; ++i) {
            int idx = t + i * 128;
            if (idx < KDIM / 16) dst[idx] = src[idx];
        }
    }
}

// ---------------- GEMM: 4 warps, 2 CTAs/SM, pipelined k-steps ------
__global__ __launch_bounds__(TPB, 2)
void gemm_kernel(float* __restrict__ sim, float* __restrict__ idxOut) {
    extern __shared__ char smem[];
    const u32 sb = smem_u32(smem);
    float* pval = reinterpret_cast<float*>(smem + NSTAGE * STAGE_BYTES);  // [128]
    int*   pidx = reinterpret_cast<int*>(pval + 128);
    const int t = threadIdx.x, lane = t & 31, wid = t >> 5;
    const int ntile = blockIdx.x, mtile = blockIdx.y;
    const int wm = wid * 32;              // warp spans all 64 cols

    const signed char* Asrc = gA + (size_t)(mtile * BM) * KDIM;
    const signed char* Bsrc = gB + (size_t)(ntile * BN) * KDIM;

    int a_row[2];
    u32 a_base[2], a_mask[2];
    #pragma unroll
    for (int mt = 0; mt < 2; ++mt) {
        a_row[mt]  = wm + mt * 16 + (lane & 15);
        a_base[mt] = (u32)a_row[mt] * 128;
        a_mask[mt] = (a_row[mt] & 7) << 4;
    }
    const u32 a_klo = (lane >> 4) * 16;
    int b_row[4];
    u32 b_base[4], b_mask[4];
    #pragma unroll
    for (int p = 0; p < 4; ++p) {
        b_row[p]  = p * 16 + ((lane >> 4) << 3) + (lane & 7);
        b_base[p] = (u32)b_row[p] * 128;
        b_mask[p] = (b_row[p] & 7) << 4;
    }
    const u32 b_klo = ((lane >> 3) & 1) * 16;

    int acc[2][8][4];
    #pragma unroll
    for (int mt = 0; mt < 2; ++mt)
        #pragma unroll
        for (int nt = 0; nt < 8; ++nt)
            #pragma unroll
            for (int i = 0; i < 4; ++i) acc[mt][nt][i] = 0;

    auto load_chunk = [&](int c, int s) {
        const u32 base = sb + s * STAGE_BYTES;
        #pragma unroll
        for (int i = 0; i < 8; ++i) {         // A: 1024 x 16B
            int idx = t + i * TPB;
            int row = idx >> 3, kc = idx & 7;
            u32 off = swz((u32)row * 128 + kc * 16);
            cp_async16(base + off, Asrc + (size_t)row * KDIM + c * BK + kc * 16);
        }
        #pragma unroll
        for (int i = 0; i < 4; ++i) {         // B: 512 x 16B
            int idx = t + i * TPB;
            int row = idx >> 3, kc = idx & 7;
            u32 off = swz((u32)row * 128 + kc * 16);
            cp_async16(base + TILE_A + off, Bsrc + (size_t)row * KDIM + c * BK + kc * 16);
        }
        asm volatile("cp.async.commit_group;" ::: "memory");
    };

    auto load_frags = [&](u32 base, u32 baseB, int ks, u32 (*a)[4], u32 (*b)[2]) {
        #pragma unroll
        for (int mt = 0; mt < 2; ++mt)
            ldsm4(a[mt], base + a_base[mt] + (((u32)ks * 32 + a_klo) ^ a_mask[mt]));
        #pragma unroll
        for (int p = 0; p < 4; ++p) {
            u32 r[4];
            ldsm4(r, baseB + b_base[p] + (((u32)ks * 32 + b_klo) ^ b_mask[p]));
            b[2 * p][0] = r[0]; b[2 * p][1] = r[1];
            b[2 * p + 1][0] = r[2]; b[2 * p + 1][1] = r[3];
        }
    };

    load_chunk(0, 0);
    load_chunk(1, 1);

    u32 af[2][2][4], bf[2][8][2];   // double-buffered k-step fragments

    for (int c = 0; c < NCHUNK; ++c) {
        if (c < NCHUNK - 1) asm volatile("cp.async.wait_group 1;" ::: "memory");
        else                asm volatile("cp.async.wait_group 0;" ::: "memory");
        __syncthreads();
        // single barrier: stage (c+2)%3 was last read during chunk c-1; every
        // warp passed this barrier only after finishing chunk c-1's compute.
        if (c + 2 < NCHUNK) load_chunk(c + 2, (c + 2) % NSTAGE);

        const u32 base  = sb + (c % NSTAGE) * STAGE_BYTES;
        const u32 baseB = base + TILE_A;
        load_frags(base, baseB, 0, af[0], bf[0]);
        #pragma unroll
        for (int ks = 0; ks < 4; ++ks) {
            const int cur = ks & 1, nxt = cur ^ 1;
            if (ks < 3) load_frags(base, baseB, ks + 1, af[nxt], bf[nxt]);
            #pragma unroll
            for (int mt = 0; mt < 2; ++mt)
                #pragma unroll
                for (int nt = 0; nt < 8; ++nt)
                    mma_s8(acc[mt][nt], af[cur][mt], bf[cur][nt]);
        }
    }

    // epilogue: dist = acc/96 + q[row]; sim = exp(-10*dist); row-argmax partial
    const int m0 = mtile * BM + wm;
    const int n0 = ntile * BN;
    float ex[2][8][4];
    #pragma unroll
    for (int mt = 0; mt < 2; ++mt) {
        const int mrow = m0 + mt * 16 + (lane >> 2);
        const float qlo = __ldg(&gQ[mrow]);
        const float qhi = __ldg(&gQ[mrow + 8]);
        #pragma unroll
        for (int nt = 0; nt < 8; ++nt) {
            const int ncol = n0 + nt * 8 + (lane & 3) * 2;
            ex[mt][nt][0] = __expf(-GAMMA_F * fmaf((float)acc[mt][nt][0], INV_SCALE, qlo));
            ex[mt][nt][1] = __expf(-GAMMA_F * fmaf((float)acc[mt][nt][1], INV_SCALE, qlo));
            ex[mt][nt][2] = __expf(-GAMMA_F * fmaf((float)acc[mt][nt][2], INV_SCALE, qhi));
            ex[mt][nt][3] = __expf(-GAMMA_F * fmaf((float)acc[mt][nt][3], INV_SCALE, qhi));
            *reinterpret_cast<float2*>(sim + (size_t)mrow * KCW + ncol) =
                make_float2(ex[mt][nt][0], ex[mt][nt][1]);
            *reinterpret_cast<float2*>(sim + (size_t)(mrow + 8) * KCW + ncol) =
                make_float2(ex[mt][nt][2], ex[mt][nt][3]);
        }
    }
    #pragma unroll
    for (int mt = 0; mt < 2; ++mt) {
        #pragma unroll
        for (int h = 0; h < 2; ++h) {
            float best = -1.f; int bidx = 0;
            #pragma unroll
            for (int nt = 0; nt < 8; ++nt) {
                const int lc = nt * 8 + (lane & 3) * 2;   // ascending within thread
                float v0 = ex[mt][nt][2 * h], v1 = ex[mt][nt][2 * h + 1];
                if (v0 > best) { best = v0; bidx = lc; }
                if (v1 > best) { best = v1; bidx = lc + 1; }
            }
            #pragma unroll
            for (int o = 1; o <= 2; o <<= 1) {
                float ov = __shfl_xor_sync(0xffffffffu, best, o);
                int   oi = __shfl_xor_sync(0xffffffffu, bidx, o);
                if (ov > best || (ov == best && oi < bidx)) { best = ov; bidx = oi; }
            }
            if ((lane & 3) == 0) {
                const int rl = wm + mt * 16 + h * 8 + (lane >> 2);
                pval[rl] = best;
                pidx[rl] = bidx;
            }
        }
    }
    __syncthreads();
    if (t < 128) {
        g_part[(size_t)(mtile * BM + t) * NTILES + ntile] =
            make_float2(pval[t], (float)(n0 + pidx[t]));
    }

    if (idxOut) {
        __threadfence();
        __shared__ int lastFlag;
        if (t == 0) lastFlag = (atomicAdd(&g_cnt[mtile], 1) == NTILES - 1);
        __syncthreads();
        if (lastFlag) {
            if (t < 128) {
                const int n = mtile * BM + t;
                float best = -1.f, bk = 0.f;
                #pragma unroll
                for (int j = 0; j < NTILES; ++j) {   // ascending k: first-max kept
                    float2 p = __ldcg(&g_part[(size_t)n * NTILES + j]);
                    if (p.x > best) { best = p.x; bk = p.y; }
                }
                idxOut[n] = bk;
            }
            if (t == 0) g_cnt[mtile] = 0;
        }
    }
}

// ---------------- launcher ----------------
extern "C" void kernel_launch(void* const* d_in, const int* in_sizes, int n_in,
                              void* d_out, int out_size) {
    const float* z = (const float*)d_in[0];
    const float* G = (const float*)d_in[1];
    const float* E = (const float*)d_in[2];

    const int N = in_sizes[0] / D;   // 2048
    const int K = in_sizes[2] / D;   // 1024

    float* out    = (float*)d_out;
    float* simPtr = nullptr;
    float* idxPtr = nullptr;
    if (out_size == N * K) {
        simPtr = out;
    } else if (out_size == N) {
        void* scratch = nullptr;
        cudaGetSymbolAddress(&scratch, g_sim_scratch);
        simPtr = (float*)scratch;
        idxPtr = out;
    } else {
        idxPtr = out;
        simPtr = out + N;
    }

    static bool attr_done = false;
    if (!attr_done) {
        cudaFuncSetAttribute(gemm_kernel,
                             cudaFuncAttributeMaxDynamicSharedMemorySize, SMEM_TOTAL);
        attr_done = true;
    }

    build_kernel<<<N + K, 128>>>(z, G, E);
    dim3 grid(K / BN, N / BM);   // (16, 16) = 256 blocks, 2 CTAs/SM
    gemm_kernel<<<grid, TPB, SMEM_TOTAL>>>(simPtr, idxPtr);
}

// round 13
// speedup vs baseline: 1.1895x; 1.1895x over previous
#include <cuda_runtime.h>
#include <math.h>
#include <stdint.h>

// LatentOddityQuantizer round 13 (= round-12 design, re-bench after infra flake):
// int8 IMMA, BK=256 super-chunks (two 128B-row sub-tiles), 3 stages x 64KB smem,
// single barrier per chunk (9 total vs 34), register double-buffered k-steps.
// Tile shape from round 10: BM=BN=128, 8 warps, warp tile 32x64.
// dist = [triW(G)|Gz]·[tri(e x e)|-2e] / 96 + zGz(fp32); exact s32 accumulation.

typedef unsigned int u32;

#define GAMMA_F 10.0f

constexpr int D     = 64;
constexpr int NPOS  = 2048;
constexpr int KCW   = 1024;
constexpr int TRI   = 2080;            // 64*65/2
constexpr int KDIM  = 2304;            // 2080 tri + 64 linear + 160 pad = 9*256
constexpr int BK    = 256;             // k-elems per super-chunk (2 sub-tiles of 128)
constexpr int NCHUNK = KDIM / BK;      // 9
constexpr int BM    = 128;
constexpr int BN    = 128;
constexpr int NSTAGE = 3;
constexpr int SUB_A  = BM * 128;                 // 16 KB per 128-col sub-tile
constexpr int SUB_B  = BN * 128;                 // 16 KB
constexpr int SUB_PAIR = SUB_A + SUB_B;          // 32 KB
constexpr int STAGE_BYTES = 2 * SUB_PAIR;        // 64 KB
constexpr int PART_BYTES  = 128 * 2 * 8;
constexpr int SMEM_TOTAL  = NSTAGE * STAGE_BYTES + PART_BYTES;  // 198656 B < 227KB cap

constexpr float SCALE_A   = 16.f;
constexpr float SCALE_B   = 6.f;
constexpr float INV_SCALE = 1.f / (16.f * 6.f);

// ---------------- device scratch ----------------
__device__ __align__(16) signed char gA[(size_t)NPOS * KDIM];
__device__ __align__(16) signed char gB[(size_t)KCW * KDIM];
__device__ float  gQ[NPOS];
__device__ float2 g_part[(size_t)NPOS * 8];
__device__ int    g_cnt[16];
__device__ float  g_sim_scratch[(size_t)NPOS * KCW];

static __device__ __forceinline__ u32 smem_u32(const void* p) {
    u32 a;
    asm("{ .reg .u64 t; cvta.to.shared.u64 t, %1; cvt.u32.u64 %0, t; }" : "=r"(a) : "l"(p));
    return a;
}
static __device__ __forceinline__ u32 swz(u32 b) { return b ^ ((b >> 3) & 0x70); }
static __device__ __forceinline__ void cp_async16(u32 dst, const void* src) {
    asm volatile("cp.async.cg.shared.global [%0], [%1], 16;" :: "r"(dst), "l"(src));
}
static __device__ __forceinline__ void ldsm4(u32* r, u32 addr) {
    asm volatile("ldmatrix.sync.aligned.m8n8.x4.shared.b16 {%0,%1,%2,%3}, [%4];"
                 : "=r"(r[0]), "=r"(r[1]), "=r"(r[2]), "=r"(r[3]) : "r"(addr));
}
static __device__ __forceinline__ void mma_s8(int* c, const u32* a, const u32* b) {
    asm volatile(
        "mma.sync.aligned.m16n8k32.row.col.s32.s8.s8.s32 "
        "{%0,%1,%2,%3}, {%4,%5,%6,%7}, {%8,%9}, {%0,%1,%2,%3};"
        : "+r"(c[0]), "+r"(c[1]), "+r"(c[2]), "+r"(c[3])
        : "r"(a[0]), "r"(a[1]), "r"(a[2]), "r"(a[3]), "r"(b[0]), "r"(b[1]));
}
static __device__ __forceinline__ signed char quant(float v, float mult) {
    int x = __float2int_rn(v * mult);
    x = max(-127, min(127, x));
    return (signed char)x;
}

// triangle bookkeeping: base(r) = r*(129-r)/2
static __device__ __forceinline__ int tri_base(int r) { return (r * (129 - r)) >> 1; }
static __device__ __forceinline__ int tri_row(int f) {
    float s = sqrtf((float)(16641 - 8 * f));
    int r = (int)((129.f - s) * 0.5f);
    if (tri_base(r + 1) <= f) ++r;
    if (tri_base(r) > f) --r;
    return r;
}

// ---------------- merged build: [0,NPOS) -> A rows (+gQ), [NPOS,..) -> B rows ----
__global__ __launch_bounds__(128)
void build_kernel(const float* __restrict__ z, const float* __restrict__ G,
                  const float* __restrict__ E) {
    __shared__ float zs[D], vs[D], qp[2];
    __shared__ __align__(16) signed char stage[KDIM];
    const int b = blockIdx.x, t = threadIdx.x;

    if (b < NPOS) {
        const int n = b;
        const float* Gn = G + (size_t)n * D * D;
        if (t < D) zs[t] = z[n * D + t];
        __syncthreads();
        if (t < D) {
            float acc = 0.f;
            #pragma unroll 8
            for (int i = 0; i < D; ++i) acc = fmaf(Gn[i * D + t], zs[i], acc);
            vs[t] = acc;
            float p = zs[t] * acc;
            #pragma unroll
            for (int o = 16; o; o >>= 1) p += __shfl_down_sync(0xffffffffu, p, o);
            if ((t & 31) == 0) qp[t >> 5] = p;
        }
        __syncthreads();
        if (t == 0) gQ[n] = qp[0] + qp[1];
        #pragma unroll
        for (int i = 0; i < 17; ++i) {
            int f = t + i * 128;
            if (f < TRI) {
                int r = tri_row(f);
                int c = r + (f - tri_base(r));
                float g = Gn[r * D + c];
                stage[f] = quant(r == c ? g : 2.f * g, SCALE_A);
            }
        }
        if (t < D) stage[TRI + t] = quant(vs[t], SCALE_A);
        for (int f = TRI + D + t; f < KDIM; f += 128) stage[f] = 0;
        __syncthreads();
        uint4* dst = reinterpret_cast<uint4*>(gA + (size_t)n * KDIM);
        const uint4* src = reinterpret_cast<const uint4*>(stage);
        #pragma unroll
        for (int i = 0; i < 2; ++i) {
            int idx = t + i * 128;
            if (idx < KDIM / 16) dst[idx] = src[idx];
        }
    } else {
        const int k = b - NPOS;
        if (t < D) zs[t] = E[(size_t)k * D + t];
        __syncthreads();
        #pragma unroll
        for (int i = 0; i < 17; ++i) {
            int f = t + i * 128;
            if (f < TRI) {
                int r = tri_row(f);
                int c = r + (f - tri_base(r));
                stage[f] = quant(zs[r] * zs[c], SCALE_B);
            }
        }
        if (t < D) stage[TRI + t] = quant(-2.f * zs[t], SCALE_B);
        for (int f = TRI + D + t; f < KDIM; f += 128) stage[f] = 0;
        __syncthreads();
        uint4* dst = reinterpret_cast<uint4*>(gB + (size_t)k * KDIM);
        const uint4* src = reinterpret_cast<const uint4*>(stage);
        #pragma unroll
        for (int i = 0; i < 2; ++i) {
            int idx = t + i * 128;
            if (idx < KDIM / 16) dst[idx] = src[idx];
        }
    }
}

// ---------------- GEMM: 8 warps, 32x64 warp tiles, BK=256, 9 barriers ----------
__global__ __launch_bounds__(256, 1)
void gemm_kernel(float* __restrict__ sim, float* __restrict__ idxOut) {
    extern __shared__ char smem[];
    const u32 sb = smem_u32(smem);
    float* pval = reinterpret_cast<float*>(smem + NSTAGE * STAGE_BYTES);  // [128][2]
    int*   pidx = reinterpret_cast<int*>(pval + 256);
    const int t = threadIdx.x, lane = t & 31, wid = t >> 5;
    const int ntile = blockIdx.x, mtile = blockIdx.y;
    const int wm = (wid & 3) * 32;
    const int wn = (wid >> 2) * 64;

    const signed char* Asrc = gA + (size_t)(mtile * BM) * KDIM;
    const signed char* Bsrc = gB + (size_t)(ntile * BN) * KDIM;

    int a_row[2];
    u32 a_base[2], a_mask[2];
    #pragma unroll
    for (int mt = 0; mt < 2; ++mt) {
        a_row[mt]  = wm + mt * 16 + (lane & 15);
        a_base[mt] = (u32)a_row[mt] * 128;
        a_mask[mt] = (a_row[mt] & 7) << 4;
    }
    const u32 a_klo = (lane >> 4) * 16;
    int b_row[4];
    u32 b_base[4], b_mask[4];
    #pragma unroll
    for (int p = 0; p < 4; ++p) {
        b_row[p]  = wn + p * 16 + ((lane >> 4) << 3) + (lane & 7);
        b_base[p] = (u32)b_row[p] * 128;
        b_mask[p] = (b_row[p] & 7) << 4;
    }
    const u32 b_klo = ((lane >> 3) & 1) * 16;

    int acc[2][8][4];
    #pragma unroll
    for (int mt = 0; mt < 2; ++mt)
        #pragma unroll
        for (int nt = 0; nt < 8; ++nt)
            #pragma unroll
            for (int i = 0; i < 4; ++i) acc[mt][nt][i] = 0;

    // one super-chunk = two 128-col sub-tiles, laid out A0|B0|A1|B1
    auto load_chunk = [&](int c, int s) {
        const u32 base = sb + s * STAGE_BYTES;
        #pragma unroll
        for (int sub = 0; sub < 2; ++sub) {
            const u32 sbase = base + sub * SUB_PAIR;
            const size_t col = (size_t)c * BK + sub * 128;
            #pragma unroll
            for (int i = 0; i < 4; ++i) {
                int idx = t + i * 256;
                int row = idx >> 3, kc = idx & 7;
                u32 off = swz((u32)row * 128 + kc * 16);
                cp_async16(sbase + off, Asrc + (size_t)row * KDIM + col + kc * 16);
                cp_async16(sbase + SUB_A + off, Bsrc + (size_t)row * KDIM + col + kc * 16);
            }
        }
        asm volatile("cp.async.commit_group;" ::: "memory");
    };

    auto load_frags = [&](u32 base, int ks8, u32 (*a)[4], u32 (*b)[2]) {
        const u32 sbase = base + (ks8 >> 2) * SUB_PAIR;
        const u32 ko = (u32)(ks8 & 3) * 32;
        #pragma unroll
        for (int mt = 0; mt < 2; ++mt)
            ldsm4(a[mt], sbase + a_base[mt] + ((ko + a_klo) ^ a_mask[mt]));
        #pragma unroll
        for (int p = 0; p < 4; ++p) {
            u32 r[4];
            ldsm4(r, sbase + SUB_A + b_base[p] + ((ko + b_klo) ^ b_mask[p]));
            b[2 * p][0] = r[0]; b[2 * p][1] = r[1];
            b[2 * p + 1][0] = r[2]; b[2 * p + 1][1] = r[3];
        }
    };

    load_chunk(0, 0);
    load_chunk(1, 1);

    u32 af[2][2][4], bf[2][8][2];   // double-buffered k-step fragments

    for (int c = 0; c < NCHUNK; ++c) {
        if (c < NCHUNK - 1) asm volatile("cp.async.wait_group 1;" ::: "memory");
        else                asm volatile("cp.async.wait_group 0;" ::: "memory");
        __syncthreads();
        // single barrier: stage (c+2)%3 was last read during chunk c-1; every
        // warp passed this barrier only after finishing chunk c-1's compute.
        if (c + 2 < NCHUNK) load_chunk(c + 2, (c + 2) % NSTAGE);

        const u32 base = sb + (c % NSTAGE) * STAGE_BYTES;
        load_frags(base, 0, af[0], bf[0]);
        #pragma unroll
        for (int ks = 0; ks < 8; ++ks) {       // 128 MMAs per warp per barrier
            const int cur = ks & 1, nxt = cur ^ 1;
            if (ks < 7) load_frags(base, ks + 1, af[nxt], bf[nxt]);
            #pragma unroll
            for (int mt = 0; mt < 2; ++mt)
                #pragma unroll
                for (int nt = 0; nt < 8; ++nt)
                    mma_s8(acc[mt][nt], af[cur][mt], bf[cur][nt]);
        }
    }

    // epilogue: dist = acc/96 + q[row]; sim = exp(-10*dist); fused row argmax
    const int m0 = mtile * BM + wm;
    const int n0 = ntile * BN + wn;
    float ex[2][8][4];
    #pragma unroll
    for (int mt = 0; mt < 2; ++mt) {
        const int mrow = m0 + mt * 16 + (lane >> 2);
        const float qlo = __ldg(&gQ[mrow]);
        const float qhi = __ldg(&gQ[mrow + 8]);
        #pragma unroll
        for (int nt = 0; nt < 8; ++nt) {
            const int ncol = n0 + nt * 8 + (lane & 3) * 2;
            ex[mt][nt][0] = __expf(-GAMMA_F * fmaf((float)acc[mt][nt][0], INV_SCALE, qlo));
            ex[mt][nt][1] = __expf(-GAMMA_F * fmaf((float)acc[mt][nt][1], INV_SCALE, qlo));
            ex[mt][nt][2] = __expf(-GAMMA_F * fmaf((float)acc[mt][nt][2], INV_SCALE, qhi));
            ex[mt][nt][3] = __expf(-GAMMA_F * fmaf((float)acc[mt][nt][3], INV_SCALE, qhi));
            *reinterpret_cast<float2*>(sim + (size_t)mrow * KCW + ncol) =
                make_float2(ex[mt][nt][0], ex[mt][nt][1]);
            *reinterpret_cast<float2*>(sim + (size_t)(mrow + 8) * KCW + ncol) =
                make_float2(ex[mt][nt][2], ex[mt][nt][3]);
        }
    }
    #pragma unroll
    for (int mt = 0; mt < 2; ++mt) {
        #pragma unroll
        for (int h = 0; h < 2; ++h) {
            float best = -1.f; int bidx = 0;
            #pragma unroll
            for (int nt = 0; nt < 8; ++nt) {
                const int lc = wn + nt * 8 + (lane & 3) * 2;
                float v0 = ex[mt][nt][2 * h], v1 = ex[mt][nt][2 * h + 1];
                if (v0 > best) { best = v0; bidx = lc; }
                if (v1 > best) { best = v1; bidx = lc + 1; }
            }
            #pragma unroll
            for (int o = 1; o <= 2; o <<= 1) {
                float ov = __shfl_xor_sync(0xffffffffu, best, o);
                int   oi = __shfl_xor_sync(0xffffffffu, bidx, o);
                if (ov > best || (ov == best && oi < bidx)) { best = ov; bidx = oi; }
            }
            if ((lane & 3) == 0) {
                const int rl = wm + mt * 16 + h * 8 + (lane >> 2);
                pval[rl * 2 + (wn >> 6)] = best;
                pidx[rl * 2 + (wn >> 6)] = bidx;
            }
        }
    }
    __syncthreads();
    if (t < 128) {
        float v0 = pval[t * 2], v1 = pval[t * 2 + 1];
        int   i0 = pidx[t * 2], i1 = pidx[t * 2 + 1];
        float best = v0; int bidx = i0;
        if (v1 > best || (v1 == best && i1 < bidx)) { best = v1; bidx = i1; }
        g_part[(size_t)(mtile * BM + t) * 8 + ntile] =
            make_float2(best, (float)(ntile * BN + bidx));
    }

    if (idxOut) {
        __threadfence();
        __shared__ int lastFlag;
        if (t == 0) lastFlag = (atomicAdd(&g_cnt[mtile], 1) == 7);
        __syncthreads();
        if (lastFlag) {
            if (t < 128) {
                const int n = mtile * BM + t;
                float best = -1.f, bk = 0.f;
                #pragma unroll
                for (int j = 0; j < 8; ++j) {   // ascending k: first-max kept
                    float2 p = __ldcg(&g_part[(size_t)n * 8 + j]);
                    if (p.x > best) { best = p.x; bk = p.y; }
                }
                idxOut[n] = bk;
            }
            if (t == 0) g_cnt[mtile] = 0;
        }
    }
}

// ---------------- launcher ----------------
extern "C" void kernel_launch(void* const* d_in, const int* in_sizes, int n_in,
                              void* d_out, int out_size) {
    const float* z = (const float*)d_in[0];
    const float* G = (const float*)d_in[1];
    const float* E = (const float*)d_in[2];

    const int N = in_sizes[0] / D;   // 2048
    const int K = in_sizes[2] / D;   // 1024

    float* out    = (float*)d_out;
    float* simPtr = nullptr;
    float* idxPtr = nullptr;
    if (out_size == N * K) {
        simPtr = out;
    } else if (out_size == N) {
        void* scratch = nullptr;
        cudaGetSymbolAddress(&scratch, g_sim_scratch);
        simPtr = (float*)scratch;
        idxPtr = out;
    } else {
        idxPtr = out;
        simPtr = out + N;
    }

    // idempotent; safe pre-capture and on replay
    cudaFuncSetAttribute(gemm_kernel,
                         cudaFuncAttributeMaxDynamicSharedMemorySize, SMEM_TOTAL);

    build_kernel<<<N + K, 128>>>(z, G, E);
    dim3 grid(K / BN, N / BM);   // (8, 16) = 128 blocks
    gemm_kernel<<<grid, 256, SMEM_TOTAL>>>(simPtr, idxPtr);
}